// round 10
// baseline (speedup 1.0000x reference)
#include <cuda_runtime.h>
#include <cuda_bf16.h>

#define D 128
#define KSTEPS 4

__global__ __launch_bounds__(256) void arccos_hess_kernel(
    const float* __restrict__ z1,
    const float* __restrict__ z2,
    float* __restrict__ out,
    int B)
{
    // grid = 3 * P, P = B/KSTEPS. CTA p of matrix m handles b = k*P + p,
    // k = 0..KSTEPS-1. At any instant the resident CTAs of a step write one
    // contiguous ~67MB window of a single matrix (R8 phase-locality), while
    // the next row's inputs are prefetched under the current store loop.
    int P   = B >> 2;               // 1024
    int bid = blockIdx.x;
    int m   = bid >= 2 * P ? 2 : (bid >= P ? 1 : 0);
    int p   = bid - m * P;

    __shared__ float a[2][D];
    __shared__ float v[2][D];
    __shared__ float part[2][3][8];

    int tid  = threadIdx.x;
    int wid  = tid >> 5;
    int lane = tid & 31;

    size_t mstride = (size_t)B * D * D;

    // Per-thread fixed j-quad (R9 structure).
    int i0 = tid >> 5;          // 0..7
    int j  = (tid & 31) << 2;   // 0..124 step 4

    // Load first row's inputs.
    float x1 = 0.f, x2 = 0.f;
    if (tid < D) {
        x1 = z1[(size_t)p * D + tid];
        x2 = z2[(size_t)p * D + tid];
    }

    #pragma unroll
    for (int k = 0; k < KSTEPS; k++) {
        int b   = k * P + p;
        int buf = k & 1;

        // Warp reduction of s11, s22, s12 for row b.
        float p11 = x1 * x1, p22 = x2 * x2, p12 = x1 * x2;
        #pragma unroll
        for (int o = 16; o; o >>= 1) {
            p11 += __shfl_down_sync(0xffffffffu, p11, o);
            p22 += __shfl_down_sync(0xffffffffu, p22, o);
            p12 += __shfl_down_sync(0xffffffffu, p12, o);
        }
        if (lane == 0) {
            part[buf][0][wid] = p11;
            part[buf][1][wid] = p22;
            part[buf][2][wid] = p12;
        }

        // Prefetch next row's inputs; latency hidden by this row's store loop.
        float nx1 = 0.f, nx2 = 0.f;
        if (k + 1 < KSTEPS && tid < D) {
            size_t nb = (size_t)((k + 1) * P + p) * D + tid;
            nx1 = z1[nb];
            nx2 = z2[nb];
        }
        __syncthreads();

        // Every thread finishes the reduction itself (broadcast LDS).
        float s11 = 0.f, s22 = 0.f, s12 = 0.f;
        #pragma unroll
        for (int w = 0; w < 8; w++) {
            s11 += part[buf][0][w];
            s22 += part[buf][1][w];
            s12 += part[buf][2][w];
        }
        float rn1 = rsqrtf(s11);
        float rn2 = rsqrtf(s22);
        float c   = s12 * rn1 * rn2;
        float c3  = 3.0f * c;
        float scale = (m == 0) ? rn1 * rn1 : (m == 1) ? rn1 * rn2 : rn2 * rn2;

        if (tid < D) {
            a[buf][tid] = x1 * rn1;
            v[buf][tid] = x2 * rn2;
        }
        __syncthreads();

        float4 aj = *reinterpret_cast<const float4*>(&a[buf][j]);
        float4 vj = *reinterpret_cast<const float4*>(&v[buf][j]);
        const float* paj = &aj.x;
        const float* pvj = &vj.x;

        float* row = out + (size_t)m * mstride + (size_t)b * D * D
                         + (size_t)i0 * D + j;

        if (m == 1) {
            // H12 = (-I + a a^T + v v^T - c * v a^T) * scale
            #pragma unroll
            for (int it = 0; it < 16; it++) {
                int i = i0 + it * 8;
                float ai = a[buf][i];
                float vi = v[buf][i];
                float4 h; float* ph = &h.x;
                int d = i - j;
                #pragma unroll
                for (int kk = 0; kk < 4; kk++) {
                    float ajk = paj[kk], vjk = pvj[kk];
                    float e = (d == kk) ? -1.f : 0.f;
                    ph[kk] = (e + ai * ajk + vi * vjk - c * vi * ajk) * scale;
                }
                __stcs(reinterpret_cast<float4*>(row), h);
                row += 8 * D;
            }
        } else if (m == 0) {
            // H11 = (c*I + a v^T + v a^T - 3c * a a^T) * scale
            #pragma unroll
            for (int it = 0; it < 16; it++) {
                int i = i0 + it * 8;
                float ai = a[buf][i];
                float vi = v[buf][i];
                float ai3 = c3 * ai;
                float4 h; float* ph = &h.x;
                int d = i - j;
                #pragma unroll
                for (int kk = 0; kk < 4; kk++) {
                    float e = (d == kk) ? c : 0.f;
                    ph[kk] = (e + ai * pvj[kk] + vi * paj[kk] - ai3 * paj[kk]) * scale;
                }
                __stcs(reinterpret_cast<float4*>(row), h);
                row += 8 * D;
            }
        } else {
            // H22 = (c*I + a v^T + v a^T - 3c * v v^T) * scale
            #pragma unroll
            for (int it = 0; it < 16; it++) {
                int i = i0 + it * 8;
                float ai = a[buf][i];
                float vi = v[buf][i];
                float vi3 = c3 * vi;
                float4 h; float* ph = &h.x;
                int d = i - j;
                #pragma unroll
                for (int kk = 0; kk < 4; kk++) {
                    float e = (d == kk) ? c : 0.f;
                    ph[kk] = (e + ai * pvj[kk] + vi * paj[kk] - vi3 * pvj[kk]) * scale;
                }
                __stcs(reinterpret_cast<float4*>(row), h);
                row += 8 * D;
            }
        }

        x1 = nx1;
        x2 = nx2;
    }
}

extern "C" void kernel_launch(void* const* d_in, const int* in_sizes, int n_in,
                              void* d_out, int out_size) {
    const float* z1 = (const float*)d_in[0];
    const float* z2 = (const float*)d_in[1];
    float* out = (float*)d_out;
    int B = in_sizes[0] / D;   // 4096
    arccos_hess_kernel<<<3 * (B / KSTEPS), 256>>>(z1, z2, out, B);
}

// round 11
// speedup vs baseline: 1.0187x; 1.0187x over previous
#include <cuda_runtime.h>
#include <cuda_bf16.h>

#define D 128

__global__ __launch_bounds__(256) void arccos_hess_kernel(
    const float* __restrict__ z1,
    const float* __restrict__ z2,
    float* __restrict__ out,
    int B)
{
    // grid = 3*B. m = matrix (0:H11, 1:H12, 2:H22); b = batch row.
    // Resident CTAs cover consecutive b within ONE matrix -> single
    // contiguous DRAM write window chip-wide at any instant.
    int bid = blockIdx.x;
    int m   = bid >= 2 * B ? 2 : (bid >= B ? 1 : 0);
    int b   = bid - m * B;

    __shared__ float a[D];   // z1 unit vector
    __shared__ float v[D];   // z2 unit vector
    __shared__ float part[3][8];

    int tid  = threadIdx.x;
    int wid  = tid >> 5;
    int lane = tid & 31;

    float x1 = 0.f, x2 = 0.f;
    if (tid < D) {
        x1 = z1[(size_t)b * D + tid];
        x2 = z2[(size_t)b * D + tid];
    }

    // Warp reduction of s11, s22, s12.
    float p11 = x1 * x1, p22 = x2 * x2, p12 = x1 * x2;
    #pragma unroll
    for (int o = 16; o; o >>= 1) {
        p11 += __shfl_down_sync(0xffffffffu, p11, o);
        p22 += __shfl_down_sync(0xffffffffu, p22, o);
        p12 += __shfl_down_sync(0xffffffffu, p12, o);
    }
    if (lane == 0) { part[0][wid] = p11; part[1][wid] = p22; part[2][wid] = p12; }
    __syncthreads();

    // Every thread finishes the reduction itself (broadcast LDS).
    float s11 = 0.f, s22 = 0.f, s12 = 0.f;
    #pragma unroll
    for (int w = 0; w < 8; w++) {
        s11 += part[0][w];
        s22 += part[1][w];
        s12 += part[2][w];
    }
    float rn1 = rsqrtf(s11);
    float rn2 = rsqrtf(s22);
    float c   = s12 * rn1 * rn2;
    float c3  = 3.0f * c;
    float scale = (m == 0) ? rn1 * rn1 : (m == 1) ? rn1 * rn2 : rn2 * rn2;

    if (tid < D) {
        a[tid] = x1 * rn1;
        v[tid] = x2 * rn2;
    }
    __syncthreads();

    size_t mstride = (size_t)B * D * D;
    float* o_m = out + (size_t)m * mstride + (size_t)b * D * D;

    // Per-thread: j-quad FIXED across all 16 iterations; i advances by 8.
    int i0 = tid >> 5;          // 0..7
    int j  = (tid & 31) << 2;   // 0,4,...,124 (fixed)

    float4 aj = *reinterpret_cast<const float4*>(&a[j]);
    float4 vj = *reinterpret_cast<const float4*>(&v[j]);
    const float* paj = &aj.x;
    const float* pvj = &vj.x;

    float* row = o_m + (size_t)i0 * D + j;

    if (m == 1) {
        // H12 = (-I + a a^T + v v^T - c * v a^T) * scale
        #pragma unroll
        for (int it = 0; it < 16; it++) {
            int i = i0 + it * 8;
            float ai = a[i];
            float vi = v[i];
            float4 h; float* ph = &h.x;
            int d = i - j;
            #pragma unroll
            for (int k = 0; k < 4; k++) {
                float ajk = paj[k], vjk = pvj[k];
                float e = (d == k) ? -1.f : 0.f;
                ph[k] = (e + ai * ajk + vi * vjk - c * vi * ajk) * scale;
            }
            __stwt(reinterpret_cast<float4*>(row), h);
            row += 8 * D;
        }
    } else {
        // H11/H22 = (c*I + a v^T + v a^T - 3c * u u^T) * scale, u = a or v.
        float4 uj;
        uj.x = (m == 0) ? paj[0] : pvj[0];
        uj.y = (m == 0) ? paj[1] : pvj[1];
        uj.z = (m == 0) ? paj[2] : pvj[2];
        uj.w = (m == 0) ? paj[3] : pvj[3];
        const float* puj = &uj.x;

        #pragma unroll
        for (int it = 0; it < 16; it++) {
            int i = i0 + it * 8;
            float ai = a[i];
            float vi = v[i];
            float ui3 = c3 * ((m == 0) ? ai : vi);
            float4 h; float* ph = &h.x;
            int d = i - j;
            #pragma unroll
            for (int k = 0; k < 4; k++) {
                float e = (d == k) ? c : 0.f;
                ph[k] = (e + ai * pvj[k] + vi * paj[k] - ui3 * puj[k]) * scale;
            }
            __stwt(reinterpret_cast<float4*>(row), h);
            row += 8 * D;
        }
    }
}

extern "C" void kernel_launch(void* const* d_in, const int* in_sizes, int n_in,
                              void* d_out, int out_size) {
    const float* z1 = (const float*)d_in[0];
    const float* z2 = (const float*)d_in[1];
    float* out = (float*)d_out;
    int B = in_sizes[0] / D;   // 4096
    arccos_hess_kernel<<<3 * B, 256>>>(z1, z2, out, B);
}

// round 13
// speedup vs baseline: 1.3678x; 1.3427x over previous
#include <cuda_runtime.h>
#include <cuda_bf16.h>

#define D 128
#define BMAX 4096

// Scratch (sanctioned: __device__ global arrays, no allocation).
__device__ float  g_ua[BMAX * D];   // z1 unit vectors
__device__ float  g_uv[BMAX * D];   // z2 unit vectors
__device__ float4 g_sc[BMAX];       // {c, i11, i12, i22} per row

// Pass 1: per-row norms, cos, unit vectors. grid=B, 128 threads.
__global__ __launch_bounds__(128) void prep_kernel(
    const float* __restrict__ z1,
    const float* __restrict__ z2)
{
    int b    = blockIdx.x;
    int tid  = threadIdx.x;
    int wid  = tid >> 5;
    int lane = tid & 31;

    __shared__ float part[3][4];

    float x1 = z1[(size_t)b * D + tid];
    float x2 = z2[(size_t)b * D + tid];

    float p11 = x1 * x1, p22 = x2 * x2, p12 = x1 * x2;
    #pragma unroll
    for (int o = 16; o; o >>= 1) {
        p11 += __shfl_down_sync(0xffffffffu, p11, o);
        p22 += __shfl_down_sync(0xffffffffu, p22, o);
        p12 += __shfl_down_sync(0xffffffffu, p12, o);
    }
    if (lane == 0) { part[0][wid] = p11; part[1][wid] = p22; part[2][wid] = p12; }
    __syncthreads();

    float s11 = 0.f, s22 = 0.f, s12 = 0.f;
    #pragma unroll
    for (int w = 0; w < 4; w++) {
        s11 += part[0][w];
        s22 += part[1][w];
        s12 += part[2][w];
    }
    float rn1 = rsqrtf(s11);
    float rn2 = rsqrtf(s22);

    g_ua[(size_t)b * D + tid] = x1 * rn1;
    g_uv[(size_t)b * D + tid] = x2 * rn2;

    if (tid == 0) {
        float4 sc;
        sc.x = s12 * rn1 * rn2;   // c
        sc.y = rn1 * rn1;         // i11
        sc.z = rn1 * rn2;         // i12
        sc.w = rn2 * rn2;         // i22
        g_sc[b] = sc;
    }
}

// Pass 2: pure store kernel. grid = 3*B, 256 threads. No smem, no syncs.
__global__ __launch_bounds__(256) void store_kernel(
    float* __restrict__ out,
    int B)
{
    int bid = blockIdx.x;
    int m   = bid >= 2 * B ? 2 : (bid >= B ? 1 : 0);
    int b   = bid - m * B;

    int tid = threadIdx.x;
    int i0  = tid >> 5;          // 0..7
    int j   = (tid & 31) << 2;   // 0..124 step 4 (fixed per thread)

    const float* ua = &g_ua[(size_t)b * D];
    const float* uv = &g_uv[(size_t)b * D];

    // 3 independent loads up front (L2/L1-hot: shared across the 3 matrix
    // CTAs of this row and reused by all warps).
    float4 sc = __ldg(&g_sc[b]);
    float4 aj = __ldg(reinterpret_cast<const float4*>(ua + j));
    float4 vj = __ldg(reinterpret_cast<const float4*>(uv + j));
    const float* paj = &aj.x;
    const float* pvj = &vj.x;

    float c     = sc.x;
    float c3    = 3.0f * c;
    float scale = (m == 0) ? sc.y : (m == 1) ? sc.z : sc.w;

    size_t mstride = (size_t)B * D * D;
    float* row = out + (size_t)m * mstride + (size_t)b * D * D
                     + (size_t)i0 * D + j;

    if (m == 1) {
        // H12 = (-I + a a^T + v v^T - c * v a^T) * scale
        #pragma unroll
        for (int it = 0; it < 16; it++) {
            int i = i0 + it * 8;
            float ai = __ldg(ua + i);   // warp-uniform, L1 hit
            float vi = __ldg(uv + i);
            float4 h; float* ph = &h.x;
            int d = i - j;
            #pragma unroll
            for (int k = 0; k < 4; k++) {
                float ajk = paj[k], vjk = pvj[k];
                float e = (d == k) ? -1.f : 0.f;
                ph[k] = (e + ai * ajk + vi * vjk - c * vi * ajk) * scale;
            }
            __stcs(reinterpret_cast<float4*>(row), h);
            row += 8 * D;
        }
    } else {
        // H11/H22 = (c*I + a v^T + v a^T - 3c * u u^T) * scale, u = a or v.
        float4 uj;
        uj.x = (m == 0) ? paj[0] : pvj[0];
        uj.y = (m == 0) ? paj[1] : pvj[1];
        uj.z = (m == 0) ? paj[2] : pvj[2];
        uj.w = (m == 0) ? paj[3] : pvj[3];
        const float* puj = &uj.x;

        #pragma unroll
        for (int it = 0; it < 16; it++) {
            int i = i0 + it * 8;
            float ai = __ldg(ua + i);
            float vi = __ldg(uv + i);
            float ui3 = c3 * ((m == 0) ? ai : vi);
            float4 h; float* ph = &h.x;
            int d = i - j;
            #pragma unroll
            for (int k = 0; k < 4; k++) {
                float e = (d == k) ? c : 0.f;
                ph[k] = (e + ai * pvj[k] + vi * paj[k] - ui3 * puj[k]) * scale;
            }
            __stcs(reinterpret_cast<float4*>(row), h);
            row += 8 * D;
        }
    }
}

extern "C" void kernel_launch(void* const* d_in, const int* in_sizes, int n_in,
                              void* d_out, int out_size) {
    const float* z1 = (const float*)d_in[0];
    const float* z2 = (const float*)d_in[1];
    float* out = (float*)d_out;
    int B = in_sizes[0] / D;   // 4096
    prep_kernel<<<B, 128>>>(z1, z2);
    store_kernel<<<3 * B, 256>>>(out, B);
}

// round 14
// speedup vs baseline: 1.4099x; 1.0308x over previous
#include <cuda_runtime.h>
#include <cuda_bf16.h>

#define D 128

__global__ __launch_bounds__(256) void arccos_hess_kernel(
    const float* __restrict__ z1,
    const float* __restrict__ z2,
    float* __restrict__ out,
    int B)
{
    // grid = 6*B. Each CTA writes HALF of one matrix (64 rows = 32KB) so the
    // scheduling tail is twice as fine. Ordering: m-major, then b, then half
    // (LSB) -> resident CTAs still form one contiguous DRAM write window.
    int bid  = blockIdx.x;
    int B2   = 2 * B;
    int m    = bid >= 2 * B2 ? 2 : (bid >= B2 ? 1 : 0);
    int sub  = bid - m * B2;
    int b    = sub >> 1;
    int half = sub & 1;          // 0: rows 0..63, 1: rows 64..127

    __shared__ float a[D];   // z1 unit vector
    __shared__ float v[D];   // z2 unit vector
    __shared__ float part[3][8];

    int tid  = threadIdx.x;
    int wid  = tid >> 5;
    int lane = tid & 31;

    float x1 = 0.f, x2 = 0.f;
    if (tid < D) {
        x1 = z1[(size_t)b * D + tid];
        x2 = z2[(size_t)b * D + tid];
    }

    // Warp reduction of s11, s22, s12.
    float p11 = x1 * x1, p22 = x2 * x2, p12 = x1 * x2;
    #pragma unroll
    for (int o = 16; o; o >>= 1) {
        p11 += __shfl_down_sync(0xffffffffu, p11, o);
        p22 += __shfl_down_sync(0xffffffffu, p22, o);
        p12 += __shfl_down_sync(0xffffffffu, p12, o);
    }
    if (lane == 0) { part[0][wid] = p11; part[1][wid] = p22; part[2][wid] = p12; }
    __syncthreads();

    // Every thread finishes the reduction itself (broadcast LDS).
    float s11 = 0.f, s22 = 0.f, s12 = 0.f;
    #pragma unroll
    for (int w = 0; w < 8; w++) {
        s11 += part[0][w];
        s22 += part[1][w];
        s12 += part[2][w];
    }
    float rn1 = rsqrtf(s11);
    float rn2 = rsqrtf(s22);
    float c   = s12 * rn1 * rn2;
    float c3  = 3.0f * c;
    float scale = (m == 0) ? rn1 * rn1 : (m == 1) ? rn1 * rn2 : rn2 * rn2;

    if (tid < D) {
        a[tid] = x1 * rn1;
        v[tid] = x2 * rn2;
    }
    __syncthreads();

    size_t mstride = (size_t)B * D * D;
    float* o_m = out + (size_t)m * mstride + (size_t)b * D * D;

    // Per-thread: j-quad fixed; i covers 8 rows spaced by 8, within this half.
    int i0 = (half << 6) + (tid >> 5);   // base row: 0..7 or 64..71
    int j  = (tid & 31) << 2;            // 0..124 step 4 (fixed)

    float4 aj = *reinterpret_cast<const float4*>(&a[j]);
    float4 vj = *reinterpret_cast<const float4*>(&v[j]);
    const float* paj = &aj.x;
    const float* pvj = &vj.x;

    float* row = o_m + (size_t)i0 * D + j;

    if (m == 1) {
        // H12 = (-I + a a^T + v v^T - c * v a^T) * scale
        #pragma unroll
        for (int it = 0; it < 8; it++) {
            int i = i0 + it * 8;
            float ai = a[i];
            float vi = v[i];
            float4 h; float* ph = &h.x;
            int d = i - j;
            #pragma unroll
            for (int k = 0; k < 4; k++) {
                float ajk = paj[k], vjk = pvj[k];
                float e = (d == k) ? -1.f : 0.f;
                ph[k] = (e + ai * ajk + vi * vjk - c * vi * ajk) * scale;
            }
            __stcs(reinterpret_cast<float4*>(row), h);
            row += 8 * D;
        }
    } else {
        // H11/H22 = (c*I + a v^T + v a^T - 3c * u u^T) * scale, u = a or v.
        float4 uj;
        uj.x = (m == 0) ? paj[0] : pvj[0];
        uj.y = (m == 0) ? paj[1] : pvj[1];
        uj.z = (m == 0) ? paj[2] : pvj[2];
        uj.w = (m == 0) ? paj[3] : pvj[3];
        const float* puj = &uj.x;

        #pragma unroll
        for (int it = 0; it < 8; it++) {
            int i = i0 + it * 8;
            float ai = a[i];
            float vi = v[i];
            float ui3 = c3 * ((m == 0) ? ai : vi);
            float4 h; float* ph = &h.x;
            int d = i - j;
            #pragma unroll
            for (int k = 0; k < 4; k++) {
                float e = (d == k) ? c : 0.f;
                ph[k] = (e + ai * pvj[k] + vi * paj[k] - ui3 * puj[k]) * scale;
            }
            __stcs(reinterpret_cast<float4*>(row), h);
            row += 8 * D;
        }
    }
}

extern "C" void kernel_launch(void* const* d_in, const int* in_sizes, int n_in,
                              void* d_out, int out_size) {
    const float* z1 = (const float*)d_in[0];
    const float* z2 = (const float*)d_in[1];
    float* out = (float*)d_out;
    int B = in_sizes[0] / D;   // 4096
    arccos_hess_kernel<<<6 * B, 256>>>(z1, z2, out, B);
}